// round 2
// baseline (speedup 1.0000x reference)
#include <cuda_runtime.h>
#include <math.h>

#define B 8
#define S 4096
#define D 1024
#define NEXP 16
#define P 4
#define H 2048
#define NP 64            // NEXP*P
#define TOK (B*S)        // 32768
#define ETOK (B*P)       // 32 tokens per expert
#define LN_EPS 1e-5f

// ---------------- static device scratch (no allocations allowed) ------------
__device__ float g_ph[D*NP];          // normalized phi * scale, layout [d][np]
__device__ float g_inv[TOK];          // 1/||x_row||
__device__ float g_logits[TOK*NP];    // [b,s,np]
__device__ float g_dspMax[B*NP];
__device__ float g_dspZ[B*NP];
__device__ double g_dspZd[B*NP];
__device__ float g_Mb[B];
__device__ double g_Zb[B];
__device__ float g_xs[B*NP*D];        // [b][np][d]
__device__ float g_h[NEXP*ETOK*H];    // [n][tok][h]
__device__ float g_r[NEXP*ETOK*D];    // [n][tok][d]
__device__ float g_ys[B*NP*D];        // [b][np][d]
__device__ float g_pmt[TOK*P];
__device__ double g_pt[B*P];
__device__ double g_mi;

// ---------------- init: xs = task_emb broadcast; zero accumulators ----------
__global__ void k_init(const float* __restrict__ task_emb) {
    int idx = blockIdx.x * 256 + threadIdx.x;      // B*NP*D = 524288 total
    if (idx < B*NP*D) {
        int d  = idx % D;
        int np = (idx / D) % NP;
        g_xs[idx] = task_emb[(np & 3) * D + d];
    }
    if (blockIdx.x == 0) {
        if (threadIdx.x < B*P) g_pt[threadIdx.x] = 0.0;
        if (threadIdx.x == 0)  g_mi = 0.0;
    }
}

// ---------------- normalize phi along D, times scale ------------------------
__global__ void k_ph(const float* __restrict__ phi, const float* __restrict__ scale) {
    int np = blockIdx.x;
    __shared__ float red[256];
    int t = threadIdx.x;
    float ss = 0.f;
    for (int d = t; d < D; d += 256) { float v = phi[d*NP + np]; ss += v*v; }
    red[t] = ss; __syncthreads();
    for (int o = 128; o > 0; o >>= 1) { if (t < o) red[t] += red[t+o]; __syncthreads(); }
    float inv = scale[0] / fmaxf(sqrtf(red[0]), 1e-12f);
    for (int d = t; d < D; d += 256)
        g_ph[d*NP + np] = phi[d*NP + np] * inv;
}

// ---------------- logits = (x . ph) * inv||x||, fused norm ------------------
__global__ void k_logits(const float* __restrict__ x) {
    __shared__ float x_sm[32*65];     // padded rows (avoid bank conflicts)
    __shared__ float ph_sm[64*64];
    __shared__ float ssq[32];
    int t = threadIdx.x;
    int tok0 = blockIdx.x * 32;
    int ty = t >> 5, tx = t & 31;
    if (t < 32) ssq[t] = 0.f;
    float acc[4][2] = {};
    __syncthreads();
    for (int d0 = 0; d0 < D; d0 += 64) {
        #pragma unroll
        for (int k = 0; k < 8; k++) {
            int i = t + k*256; int tk = i >> 6, dd = i & 63;
            x_sm[tk*65 + dd] = x[(size_t)(tok0+tk)*D + d0 + dd];
        }
        #pragma unroll
        for (int k = 0; k < 16; k++) {
            int i = t + k*256; int dd = i >> 6, np = i & 63;
            ph_sm[dd*64 + np] = g_ph[(d0+dd)*NP + np];
        }
        __syncthreads();
        // sum of squares: warp ty covers tokens 4*ty..4*ty+3
        #pragma unroll
        for (int i = 0; i < 4; i++) {
            int tk = ty*4 + i;
            float v1 = x_sm[tk*65 + tx], v2 = x_sm[tk*65 + tx + 32];
            float s = v1*v1 + v2*v2;
            #pragma unroll
            for (int o = 16; o > 0; o >>= 1) s += __shfl_xor_sync(~0u, s, o);
            if (tx == 0) ssq[tk] += s;
        }
        // GEMM tile
        #pragma unroll 4
        for (int dd = 0; dd < 64; dd++) {
            float p0 = ph_sm[dd*64 + tx];
            float p1 = ph_sm[dd*64 + tx + 32];
            #pragma unroll
            for (int i = 0; i < 4; i++) {
                float xv = x_sm[(ty*4+i)*65 + dd];
                acc[i][0] += xv * p0;
                acc[i][1] += xv * p1;
            }
        }
        __syncthreads();
    }
    if (t < 32) {
        float inv = 1.f / fmaxf(sqrtf(ssq[t]), 1e-12f);
        g_inv[tok0 + t] = inv;
        ssq[t] = inv;
    }
    __syncthreads();
    #pragma unroll
    for (int i = 0; i < 4; i++) {
        int tk = ty*4 + i;
        float inv = ssq[tk];
        g_logits[(size_t)(tok0+tk)*NP + tx]      = acc[i][0] * inv;
        g_logits[(size_t)(tok0+tk)*NP + tx + 32] = acc[i][1] * inv;
    }
}

// ---------------- per-(b,np) column softmax stats over S --------------------
__global__ void k_colstats() {
    int b  = blockIdx.x >> 6;
    int np = blockIdx.x & 63;
    __shared__ float red[256];
    __shared__ double redd[256];
    int t = threadIdx.x;
    const float* base = g_logits + (size_t)b*S*NP + np;
    float m = -1e30f;
    for (int s = t; s < S; s += 256) m = fmaxf(m, base[(size_t)s*NP]);
    red[t] = m; __syncthreads();
    for (int o = 128; o > 0; o >>= 1) { if (t < o) red[t] = fmaxf(red[t], red[t+o]); __syncthreads(); }
    float M = red[0]; __syncthreads();
    double z = 0.0;
    for (int s = t; s < S; s += 256) z += exp((double)(base[(size_t)s*NP] - M));
    redd[t] = z; __syncthreads();
    for (int o = 128; o > 0; o >>= 1) { if (t < o) redd[t] += redd[t+o]; __syncthreads(); }
    if (t == 0) {
        g_dspMax[b*NP+np] = M;
        g_dspZd[b*NP+np]  = redd[0];
        g_dspZ[b*NP+np]   = (float)redd[0];
    }
}

// ---------------- per-batch flat softmax stats ------------------------------
__global__ void k_batchstats() {
    int w = threadIdx.x >> 5;     // batch
    int lane = threadIdx.x & 31;
    float m1 = g_dspMax[w*NP + lane], m2 = g_dspMax[w*NP + lane + 32];
    float m = fmaxf(m1, m2);
    #pragma unroll
    for (int o = 16; o > 0; o >>= 1) m = fmaxf(m, __shfl_xor_sync(~0u, m, o));
    double z = exp((double)(m1 - m)) * g_dspZd[w*NP + lane]
             + exp((double)(m2 - m)) * g_dspZd[w*NP + lane + 32];
    #pragma unroll
    for (int o = 16; o > 0; o >>= 1) z += __shfl_xor_sync(~0u, z, o);
    if (lane == 0) { g_Mb[w] = m; g_Zb[w] = z; }
}

// ---------------- cmb softmax (to out) + mutual-info partials ---------------
__global__ void k_cmb(float* __restrict__ out_cmb) {
    __shared__ double pt_sm[P];
    int t = threadIdx.x, w = t >> 5, lane = t & 31;
    if (t < P) pt_sm[t] = 0.0;
    __syncthreads();
    int tok = blockIdx.x * 8 + w;
    int b = tok >> 12;
    const float* lrow = g_logits + (size_t)tok*NP;
    float l1 = lrow[lane], l2 = lrow[lane + 32];
    float m = fmaxf(l1, l2);
    #pragma unroll
    for (int o = 16; o > 0; o >>= 1) m = fmaxf(m, __shfl_xor_sync(~0u, m, o));
    float e1 = expf(l1 - m), e2 = expf(l2 - m);
    float z = e1 + e2;
    #pragma unroll
    for (int o = 16; o > 0; o >>= 1) z += __shfl_xor_sync(~0u, z, o);
    float iz = 1.f / z;
    out_cmb[(size_t)tok*NP + lane]      = e1 * iz;
    out_cmb[(size_t)tok*NP + lane + 32] = e2 * iz;
    // flat softmax (double): lane holds np=lane (n=lane/4) and np=lane+32, same p
    float Mb = g_Mb[b];
    double iZb = 1.0 / g_Zb[b];
    double f = (exp((double)(l1 - Mb)) + exp((double)(l2 - Mb))) * iZb;
    f += __shfl_xor_sync(~0u, f, 4);
    f += __shfl_xor_sync(~0u, f, 8);
    f += __shfl_xor_sync(~0u, f, 16);
    if (lane < P) {
        g_pmt[tok*P + lane] = (float)f;
        atomicAdd(&pt_sm[lane], f);
    }
    __syncthreads();
    if (t < P) atomicAdd(&g_pt[b*P + t], pt_sm[t]);
}

// ---------------- xs = sum_s xn * dsp  (per-batch [64,S]x[S,D]) -------------
__global__ void k_xs(const float* __restrict__ x) {
    __shared__ float x_sm[32*128];
    __shared__ float w_sm[32*64];
    __shared__ float mM[64], rz[64];
    int t = threadIdx.x;
    int b = blockIdx.z, d0 = blockIdx.y * 128, s0 = blockIdx.x * 512;
    if (t < 64) { mM[t] = g_dspMax[b*NP + t]; rz[t] = 1.f / g_dspZ[b*NP + t]; }
    int ty = t >> 4, tx = t & 15;
    float acc[4][8] = {};
    __syncthreads();
    for (int st = 0; st < 512; st += 32) {
        int sbase = b*S + s0 + st;
        #pragma unroll
        for (int k = 0; k < 8; k++) {
            int i = t + k*256; int ss = i >> 6, np = i & 63;
            float l = g_logits[(size_t)(sbase+ss)*NP + np];
            w_sm[ss*64 + np] = expf(l - mM[np]) * rz[np] * g_inv[sbase+ss];
        }
        #pragma unroll
        for (int k = 0; k < 16; k++) {
            int i = t + k*256; int ss = i >> 7, dd = i & 127;
            x_sm[ss*128 + dd] = x[(size_t)(sbase+ss)*D + d0 + dd];
        }
        __syncthreads();
        #pragma unroll 2
        for (int ss = 0; ss < 32; ss++) {
            float wf[4], xf[8];
            #pragma unroll
            for (int a = 0; a < 4; a++) wf[a] = w_sm[ss*64 + ty + 16*a];
            #pragma unroll
            for (int j = 0; j < 8; j++) xf[j] = x_sm[ss*128 + tx + 16*j];
            #pragma unroll
            for (int a = 0; a < 4; a++)
                #pragma unroll
                for (int j = 0; j < 8; j++) acc[a][j] += wf[a] * xf[j];
        }
        __syncthreads();
    }
    #pragma unroll
    for (int a = 0; a < 4; a++)
        #pragma unroll
        for (int j = 0; j < 8; j++)
            atomicAdd(&g_xs[(size_t)(b*NP + ty + 16*a)*D + d0 + tx + 16*j], acc[a][j]);
}

// ---------------- expert FFN layer 1: h = silu(xs@W1 + b1) ------------------
__global__ void k_ffn1(const float* __restrict__ W1, const float* __restrict__ b1) {
    __shared__ float a_sm[32*65];
    __shared__ float w_sm[64*128];
    int t = threadIdx.x;
    int n = blockIdx.x, h0 = blockIdx.y * 128;
    int ty = t >> 5, tx = t & 31;
    float acc[4][4] = {};
    const float* Wbase = W1 + (size_t)n*D*H + h0;
    for (int d0 = 0; d0 < D; d0 += 64) {
        #pragma unroll
        for (int k = 0; k < 8; k++) {
            int i = t + k*256; int tk = i >> 6, dd = i & 63;
            int bb = tk >> 2, pp = tk & 3;
            a_sm[tk*65 + dd] = g_xs[(size_t)(bb*NP + n*4 + pp)*D + d0 + dd];
        }
        #pragma unroll
        for (int k = 0; k < 32; k++) {
            int i = t + k*256; int dd = i >> 7, hh = i & 127;
            w_sm[dd*128 + hh] = Wbase[(size_t)(d0+dd)*H + hh];
        }
        __syncthreads();
        #pragma unroll 4
        for (int dd = 0; dd < 64; dd++) {
            float xf[4], wf[4];
            #pragma unroll
            for (int i = 0; i < 4; i++) xf[i] = a_sm[(ty*4+i)*65 + dd];
            #pragma unroll
            for (int j = 0; j < 4; j++) wf[j] = w_sm[dd*128 + tx + 32*j];
            #pragma unroll
            for (int i = 0; i < 4; i++)
                #pragma unroll
                for (int j = 0; j < 4; j++) acc[i][j] += xf[i] * wf[j];
        }
        __syncthreads();
    }
    #pragma unroll
    for (int i = 0; i < 4; i++) {
        int tk = ty*4 + i;
        #pragma unroll
        for (int j = 0; j < 4; j++) {
            int hh = tx + 32*j;
            float v = acc[i][j] + b1[n*H + h0 + hh];
            v = v / (1.f + expf(-v));                   // silu
            g_h[((size_t)n*ETOK + tk)*H + h0 + hh] = v;
        }
    }
}

// ---------------- expert FFN layer 2: r = xs + h@W2 + b2 --------------------
__global__ void k_ffn2(const float* __restrict__ W2, const float* __restrict__ b2) {
    __shared__ float a_sm[32*65];
    __shared__ float w_sm[64*128];
    int t = threadIdx.x;
    int n = blockIdx.x, d0 = blockIdx.y * 128;
    int ty = t >> 5, tx = t & 31;
    float acc[4][4] = {};
    const float* Wbase = W2 + (size_t)n*H*D + d0;
    for (int h0 = 0; h0 < H; h0 += 64) {
        #pragma unroll
        for (int k = 0; k < 8; k++) {
            int i = t + k*256; int tk = i >> 6, dd = i & 63;
            a_sm[tk*65 + dd] = g_h[((size_t)n*ETOK + tk)*H + h0 + dd];
        }
        #pragma unroll
        for (int k = 0; k < 32; k++) {
            int i = t + k*256; int dd = i >> 7, hh = i & 127;
            w_sm[dd*128 + hh] = Wbase[(size_t)(h0+dd)*D + hh];
        }
        __syncthreads();
        #pragma unroll 4
        for (int dd = 0; dd < 64; dd++) {
            float xf[4], wf[4];
            #pragma unroll
            for (int i = 0; i < 4; i++) xf[i] = a_sm[(ty*4+i)*65 + dd];
            #pragma unroll
            for (int j = 0; j < 4; j++) wf[j] = w_sm[dd*128 + tx + 32*j];
            #pragma unroll
            for (int i = 0; i < 4; i++)
                #pragma unroll
                for (int j = 0; j < 4; j++) acc[i][j] += xf[i] * wf[j];
        }
        __syncthreads();
    }
    #pragma unroll
    for (int i = 0; i < 4; i++) {
        int tk = ty*4 + i;
        int bb = tk >> 2, pp = tk & 3;
        #pragma unroll
        for (int j = 0; j < 4; j++) {
            int dd = tx + 32*j;
            float xsv = g_xs[(size_t)(bb*NP + n*4 + pp)*D + d0 + dd];
            g_r[((size_t)n*ETOK + tk)*D + d0 + dd] = xsv + acc[i][j] + b2[n*D + d0 + dd];
        }
    }
}

// ---------------- LayerNorm per expert-token row ----------------------------
__global__ void k_ln(const float* __restrict__ ln_g, const float* __restrict__ ln_b) {
    int row = blockIdx.x;                 // n*32 + tok
    int n = row >> 5, tk = row & 31;
    int t = threadIdx.x;
    const float* r = g_r + (size_t)row*D;
    float v[4]; float s = 0.f, s2 = 0.f;
    #pragma unroll
    for (int k = 0; k < 4; k++) { v[k] = r[t + k*256]; s += v[k]; s2 += v[k]*v[k]; }
    __shared__ float rs[256], rs2[256];
    rs[t] = s; rs2[t] = s2; __syncthreads();
    for (int o = 128; o > 0; o >>= 1) {
        if (t < o) { rs[t] += rs[t+o]; rs2[t] += rs2[t+o]; }
        __syncthreads();
    }
    float mu = rs[0] / D;
    float var = rs2[0] / D - mu*mu;
    float rstd = rsqrtf(var + LN_EPS);
    int bb = tk >> 2, pp = tk & 3;
    float* o = g_ys + (size_t)(bb*NP + n*4 + pp)*D;
    #pragma unroll
    for (int k = 0; k < 4; k++) {
        int d = t + k*256;
        o[d] = (v[k] - mu) * rstd * ln_g[n*D + d] + ln_b[n*D + d];
    }
}

// ---------------- combine: y[b,m,p,d] = sum_n ys * cmb ----------------------
__global__ void k_combine(const float* __restrict__ cmb, float* __restrict__ out) {
    __shared__ float ys_sm[64*128];
    __shared__ float cmb_sm[8*64];
    int t = threadIdx.x;
    int b = blockIdx.z, d0 = blockIdx.y * 128, s0 = blockIdx.x * 128;
    #pragma unroll
    for (int k = 0; k < 32; k++) {
        int i = t + k*256; int np = i >> 7, dd = i & 127;
        ys_sm[np*128 + dd] = g_ys[(size_t)(b*NP + np)*D + d0 + dd];
    }
    int phalf = t >> 7;
    int dd = t & 127;
    for (int tg = 0; tg < 128; tg += 8) {
        __syncthreads();
        #pragma unroll
        for (int k = 0; k < 2; k++) {
            int i = t + k*256; int tk = i >> 6, np = i & 63;
            cmb_sm[tk*64 + np] = cmb[(size_t)(b*S + s0 + tg + tk)*NP + np];
        }
        __syncthreads();
        #pragma unroll 2
        for (int tk = 0; tk < 8; tk++) {
            int s = s0 + tg + tk;
            #pragma unroll
            for (int pi = 0; pi < 2; pi++) {
                int p = phalf*2 + pi;
                float acc = 0.f;
                #pragma unroll
                for (int n = 0; n < NEXP; n++)
                    acc += ys_sm[(n*4+p)*128 + dd] * cmb_sm[tk*64 + n*4 + p];
                out[((size_t)p*B + b)*S*D + (size_t)s*D + d0 + dd] = acc;
            }
        }
    }
}

// ---------------- mutual info loss ------------------------------------------
__global__ void k_mi() {
    __shared__ double red[256];
    int t = threadIdx.x;
    int tok = blockIdx.x * 256 + t;
    int b = tok >> 12;
    float pv[P]; double pm = 0.0;
    #pragma unroll
    for (int p = 0; p < P; p++) { pv[p] = g_pmt[tok*P + p]; pm += (double)pv[p]; }
    double term = 0.0;
    #pragma unroll
    for (int p = 0; p < P; p++) {
        double ratio = (double)pv[p] / (pm * g_pt[b*P + p]) + 1e-10;
        term += (double)pv[p] * log(ratio);
    }
    red[t] = term; __syncthreads();
    for (int o = 128; o > 0; o >>= 1) { if (t < o) red[t] += red[t+o]; __syncthreads(); }
    if (t == 0) atomicAdd(&g_mi, red[0]);
}

__global__ void k_fin(float* __restrict__ out_mi) {
    out_mi[0] = (float)(-g_mi);
}

// ---------------- launch -----------------------------------------------------
extern "C" void kernel_launch(void* const* d_in, const int* in_sizes, int n_in,
                              void* d_out, int out_size) {
    const float* x        = (const float*)d_in[0];
    const float* phi      = (const float*)d_in[1];
    const float* scale    = (const float*)d_in[2];
    const float* task_emb = (const float*)d_in[3];
    const float* W1       = (const float*)d_in[4];
    const float* b1       = (const float*)d_in[5];
    const float* W2       = (const float*)d_in[6];
    const float* b2       = (const float*)d_in[7];
    const float* ln_g     = (const float*)d_in[8];
    const float* ln_b     = (const float*)d_in[9];
    float* out = (float*)d_out;
    float* out_cmb = out + (size_t)P*B*S*D;
    float* out_mi  = out_cmb + (size_t)B*S*NP;

    k_init<<<2048, 256>>>(task_emb);
    k_ph<<<NP, 256>>>(phi, scale);
    k_logits<<<TOK/32, 256>>>(x);
    k_colstats<<<B*NP, 256>>>();
    k_batchstats<<<1, 256>>>();
    k_cmb<<<TOK/8, 256>>>(out_cmb);
    k_xs<<<dim3(8, 8, B), 256>>>(x);
    k_ffn1<<<dim3(NEXP, H/128), 256>>>(W1, b1);
    k_ffn2<<<dim3(NEXP, D/128), 256>>>(W2, b2);
    k_ln<<<NEXP*ETOK, 256>>>(ln_g, ln_b);
    k_combine<<<dim3(32, 8, B), 256>>>(out_cmb, out);
    k_mi<<<TOK/256, 256>>>();
    k_fin<<<1, 1>>>(out_mi);
}

// round 3
// speedup vs baseline: 1.8378x; 1.8378x over previous
#include <cuda_runtime.h>
#include <math.h>

#define B 8
#define S 4096
#define D 1024
#define NEXP 16
#define P 4
#define H 2048
#define NP 64            // NEXP*P
#define TOK (B*S)        // 32768
#define ETOK (B*P)       // 32 tokens per expert
#define LN_EPS 1e-5f

// ---------------- static device scratch (no allocations allowed) ------------
__device__ float  g_ph[D*NP];          // normalized phi * scale, layout [d][np]
__device__ float  g_wnum[TOK*NP];      // exp(l-shift) * inv||x||  (dispatch numerator)
__device__ float  g_epart[TOK*P];      // sum_n exp(l-shift)  (flat-softmax numerator per p)
__device__ double g_Zd[B*NP];          // dispatch softmax denominators (no inv folded)
__device__ float  g_Zf[B*NP];          // 1/Zd as float
__device__ double g_Zb[B];             // flat softmax denominator
__device__ double g_iZb[B];
__device__ double g_ptn[B*P];          // sum_s epart (unnormalized p_t * Zb)
__device__ float  g_shift;             // |scale| : constant softmax shift
__device__ float  g_xs[B*NP*D];        // [b][np][d]
__device__ float  g_h[NEXP*ETOK*H];    // [n][tok][h]
__device__ float  g_r[NEXP*ETOK*D];    // [n][tok][d]
__device__ float  g_ys[B*NP*D];        // [b][np][d]
__device__ double g_mi;

// ---------------- init: xs = task_emb broadcast; zero accumulators ----------
__global__ void k_init(const float* __restrict__ task_emb) {
    int idx = blockIdx.x * 256 + threadIdx.x;      // B*NP*D = 524288 total
    if (idx < B*NP*D) {
        int d  = idx % D;
        int np = (idx / D) % NP;
        g_xs[idx] = task_emb[(np & 3) * D + d];
    }
    if (blockIdx.x < 2) g_Zd[blockIdx.x * 256 + threadIdx.x] = 0.0;
    if (blockIdx.x == 2) {
        if (threadIdx.x < B*P) g_ptn[threadIdx.x] = 0.0;
        if (threadIdx.x == 0)  g_mi = 0.0;
    }
}

// ---------------- normalize phi along D, times scale ------------------------
__global__ void k_ph(const float* __restrict__ phi, const float* __restrict__ scale) {
    int np = blockIdx.x;
    __shared__ float red[256];
    int t = threadIdx.x;
    float ss = 0.f;
    for (int d = t; d < D; d += 256) { float v = phi[d*NP + np]; ss += v*v; }
    red[t] = ss; __syncthreads();
    for (int o = 128; o > 0; o >>= 1) { if (t < o) red[t] += red[t+o]; __syncthreads(); }
    float inv = scale[0] / fmaxf(sqrtf(red[0]), 1e-12f);
    for (int d = t; d < D; d += 256)
        g_ph[d*NP + np] = phi[d*NP + np] * inv;
    if (np == 0 && t == 0) g_shift = fabsf(scale[0]);
}

// ---------------- logits GEMM + fused softmax epilogues ---------------------
// Computes l = (x.ph)*inv||x||, then in-register:
//   - cmb row softmax  -> out_cmb
//   - dispatch numerator e*inv -> g_wnum
//   - per-(b,np) Z sums -> g_Zd (double atomics)
//   - per-(tok,p) flat numerators -> g_epart, block-summed -> g_ptn
__global__ void k_logits(const float* __restrict__ x, float* __restrict__ out_cmb) {
    __shared__ float x_sm[32*65];     // padded rows (avoid bank conflicts)
    __shared__ float ph_sm[64*64];
    __shared__ float ssq[32];
    __shared__ float zred[64*8];
    __shared__ float ep_sm[32*4];
    int t = threadIdx.x;
    int tok0 = blockIdx.x * 32;
    int b = tok0 >> 12;
    int ty = t >> 5, tx = t & 31;
    if (t < 32) ssq[t] = 0.f;
    float acc[4][2] = {};
    __syncthreads();
    for (int d0 = 0; d0 < D; d0 += 64) {
        #pragma unroll
        for (int k = 0; k < 8; k++) {
            int i = t + k*256; int tk = i >> 6, dd = i & 63;
            x_sm[tk*65 + dd] = x[(size_t)(tok0+tk)*D + d0 + dd];
        }
        #pragma unroll
        for (int k = 0; k < 16; k++) {
            int i = t + k*256; int dd = i >> 6, np = i & 63;
            ph_sm[dd*64 + np] = g_ph[(d0+dd)*NP + np];
        }
        __syncthreads();
        // sum of squares: warp ty covers tokens 4*ty..4*ty+3
        #pragma unroll
        for (int i = 0; i < 4; i++) {
            int tk = ty*4 + i;
            float v1 = x_sm[tk*65 + tx], v2 = x_sm[tk*65 + tx + 32];
            float s = v1*v1 + v2*v2;
            #pragma unroll
            for (int o = 16; o > 0; o >>= 1) s += __shfl_xor_sync(~0u, s, o);
            if (tx == 0) ssq[tk] += s;
        }
        // GEMM tile
        #pragma unroll 4
        for (int dd = 0; dd < 64; dd++) {
            float p0 = ph_sm[dd*64 + tx];
            float p1 = ph_sm[dd*64 + tx + 32];
            #pragma unroll
            for (int i = 0; i < 4; i++) {
                float xv = x_sm[(ty*4+i)*65 + dd];
                acc[i][0] += xv * p0;
                acc[i][1] += xv * p1;
            }
        }
        __syncthreads();
    }
    if (t < 32) ssq[t] = 1.f / fmaxf(sqrtf(ssq[t]), 1e-12f);
    __syncthreads();
    float shift = g_shift;
    float zsum0 = 0.f, zsum1 = 0.f;
    #pragma unroll
    for (int i = 0; i < 4; i++) {
        int tk = ty*4 + i;
        size_t tok = tok0 + tk;
        float inv = ssq[tk];
        float e0 = expf(acc[i][0]*inv - shift);
        float e1 = expf(acc[i][1]*inv - shift);
        // cmb row softmax (over 64 np spread across the warp)
        float z = e0 + e1;
        #pragma unroll
        for (int o = 16; o > 0; o >>= 1) z += __shfl_xor_sync(~0u, z, o);
        float izr = 1.f / z;
        out_cmb[tok*NP + tx]      = e0 * izr;
        out_cmb[tok*NP + tx + 32] = e1 * izr;
        // dispatch numerator with 1/||x|| folded
        g_wnum[tok*NP + tx]      = e0 * inv;
        g_wnum[tok*NP + tx + 32] = e1 * inv;
        // flat numerators per p (sum over n: lanes with same tx&3)
        float f = e0 + e1;
        f += __shfl_xor_sync(~0u, f, 4);
        f += __shfl_xor_sync(~0u, f, 8);
        f += __shfl_xor_sync(~0u, f, 16);
        if (tx < P) { g_epart[tok*P + tx] = f; ep_sm[tk*P + tx] = f; }
        zsum0 += e0; zsum1 += e1;
    }
    zred[tx*8 + ty] = zsum0;
    zred[(tx+32)*8 + ty] = zsum1;
    __syncthreads();
    if (t < 64) {
        float s = 0.f;
        #pragma unroll
        for (int k = 0; k < 8; k++) s += zred[t*8 + k];
        atomicAdd(&g_Zd[b*NP + t], (double)s);
    }
    if (t < P) {
        float s = 0.f;
        #pragma unroll
        for (int k = 0; k < 32; k++) s += ep_sm[k*P + t];
        atomicAdd(&g_ptn[b*P + t], (double)s);
    }
}

// ---------------- finish Z stats --------------------------------------------
__global__ void k_zb() {
    int t = threadIdx.x, w = t >> 5, lane = t & 31;
    if (w < B) {
        double z = g_Zd[w*NP + lane] + g_Zd[w*NP + lane + 32];
        #pragma unroll
        for (int o = 16; o > 0; o >>= 1) z += __shfl_xor_sync(~0u, z, o);
        if (lane == 0) { g_Zb[w] = z; g_iZb[w] = 1.0 / z; }
    }
    for (int i = t; i < B*NP; i += 256) g_Zf[i] = (float)(1.0 / g_Zd[i]);
}

// ---------------- xs = sum_s xn * dsp  (per-batch [64,S]x[S,D]) -------------
__global__ void k_xs(const float* __restrict__ x) {
    __shared__ float x_sm[32*128];
    __shared__ float w_sm[32*64];
    __shared__ float rz[64];
    int t = threadIdx.x;
    int b = blockIdx.z, d0 = blockIdx.y * 128, s0 = blockIdx.x * 512;
    if (t < 64) rz[t] = g_Zf[b*NP + t];
    int ty = t >> 4, tx = t & 15;
    float acc[4][8] = {};
    __syncthreads();
    for (int st = 0; st < 512; st += 32) {
        int sbase = b*S + s0 + st;
        #pragma unroll
        for (int k = 0; k < 8; k++) {
            int i = t + k*256; int ss = i >> 6, np = i & 63;
            w_sm[ss*64 + np] = g_wnum[(size_t)(sbase+ss)*NP + np] * rz[np];
        }
        #pragma unroll
        for (int k = 0; k < 16; k++) {
            int i = t + k*256; int ss = i >> 7, dd = i & 127;
            x_sm[ss*128 + dd] = x[(size_t)(sbase+ss)*D + d0 + dd];
        }
        __syncthreads();
        #pragma unroll 2
        for (int ss = 0; ss < 32; ss++) {
            float wf[4], xf[8];
            #pragma unroll
            for (int a = 0; a < 4; a++) wf[a] = w_sm[ss*64 + ty + 16*a];
            #pragma unroll
            for (int j = 0; j < 8; j++) xf[j] = x_sm[ss*128 + tx + 16*j];
            #pragma unroll
            for (int a = 0; a < 4; a++)
                #pragma unroll
                for (int j = 0; j < 8; j++) acc[a][j] += wf[a] * xf[j];
        }
        __syncthreads();
    }
    #pragma unroll
    for (int a = 0; a < 4; a++)
        #pragma unroll
        for (int j = 0; j < 8; j++)
            atomicAdd(&g_xs[(size_t)(b*NP + ty + 16*a)*D + d0 + tx + 16*j], acc[a][j]);
}

// ---------------- expert FFN layer 1: h = silu(xs@W1 + b1), 64-wide tiles ---
__global__ void k_ffn1(const float* __restrict__ W1, const float* __restrict__ b1) {
    __shared__ float a_sm[32*65];
    __shared__ float w_sm[64*64];
    int t = threadIdx.x;
    int n = blockIdx.x, h0 = blockIdx.y * 64;
    int ty = t >> 5, tx = t & 31;
    float acc[4][2] = {};
    const float* Wbase = W1 + (size_t)n*D*H + h0;
    for (int d0 = 0; d0 < D; d0 += 64) {
        #pragma unroll
        for (int k = 0; k < 8; k++) {
            int i = t + k*256; int tk = i >> 6, dd = i & 63;
            int bb = tk >> 2, pp = tk & 3;
            a_sm[tk*65 + dd] = g_xs[(size_t)(bb*NP + n*4 + pp)*D + d0 + dd];
        }
        #pragma unroll
        for (int k = 0; k < 16; k++) {
            int i = t + k*256; int dd = i >> 6, hh = i & 63;
            w_sm[dd*64 + hh] = Wbase[(size_t)(d0+dd)*H + hh];
        }
        __syncthreads();
        #pragma unroll 4
        for (int dd = 0; dd < 64; dd++) {
            float w0 = w_sm[dd*64 + tx];
            float w1 = w_sm[dd*64 + tx + 32];
            #pragma unroll
            for (int i = 0; i < 4; i++) {
                float xv = a_sm[(ty*4+i)*65 + dd];
                acc[i][0] += xv * w0;
                acc[i][1] += xv * w1;
            }
        }
        __syncthreads();
    }
    #pragma unroll
    for (int i = 0; i < 4; i++) {
        int tk = ty*4 + i;
        #pragma unroll
        for (int j = 0; j < 2; j++) {
            int hh = tx + 32*j;
            float v = acc[i][j] + b1[n*H + h0 + hh];
            v = v / (1.f + expf(-v));                   // silu
            g_h[((size_t)n*ETOK + tk)*H + h0 + hh] = v;
        }
    }
}

// ---------------- expert FFN layer 2: r = xs + h@W2 + b2, 64-wide tiles -----
__global__ void k_ffn2(const float* __restrict__ W2, const float* __restrict__ b2) {
    __shared__ float a_sm[32*65];
    __shared__ float w_sm[64*64];
    int t = threadIdx.x;
    int n = blockIdx.x, d0 = blockIdx.y * 64;
    int ty = t >> 5, tx = t & 31;
    float acc[4][2] = {};
    const float* Wbase = W2 + (size_t)n*H*D + d0;
    for (int h0 = 0; h0 < H; h0 += 64) {
        #pragma unroll
        for (int k = 0; k < 8; k++) {
            int i = t + k*256; int tk = i >> 6, dd = i & 63;
            a_sm[tk*65 + dd] = g_h[((size_t)n*ETOK + tk)*H + h0 + dd];
        }
        #pragma unroll
        for (int k = 0; k < 16; k++) {
            int i = t + k*256; int dd = i >> 6, hh = i & 63;
            w_sm[dd*64 + hh] = Wbase[(size_t)(h0+dd)*D + hh];
        }
        __syncthreads();
        #pragma unroll 4
        for (int dd = 0; dd < 64; dd++) {
            float w0 = w_sm[dd*64 + tx];
            float w1 = w_sm[dd*64 + tx + 32];
            #pragma unroll
            for (int i = 0; i < 4; i++) {
                float xv = a_sm[(ty*4+i)*65 + dd];
                acc[i][0] += xv * w0;
                acc[i][1] += xv * w1;
            }
        }
        __syncthreads();
    }
    #pragma unroll
    for (int i = 0; i < 4; i++) {
        int tk = ty*4 + i;
        int bb = tk >> 2, pp = tk & 3;
        #pragma unroll
        for (int j = 0; j < 2; j++) {
            int dd = tx + 32*j;
            float xsv = g_xs[(size_t)(bb*NP + n*4 + pp)*D + d0 + dd];
            g_r[((size_t)n*ETOK + tk)*D + d0 + dd] = xsv + acc[i][j] + b2[n*D + d0 + dd];
        }
    }
}

// ---------------- LayerNorm per expert-token row ----------------------------
__global__ void k_ln(const float* __restrict__ ln_g, const float* __restrict__ ln_b) {
    int row = blockIdx.x;                 // n*32 + tok
    int n = row >> 5, tk = row & 31;
    int t = threadIdx.x;
    const float* r = g_r + (size_t)row*D;
    float v[4]; float s = 0.f, s2 = 0.f;
    #pragma unroll
    for (int k = 0; k < 4; k++) { v[k] = r[t + k*256]; s += v[k]; s2 += v[k]*v[k]; }
    __shared__ float rs[256], rs2[256];
    rs[t] = s; rs2[t] = s2; __syncthreads();
    for (int o = 128; o > 0; o >>= 1) {
        if (t < o) { rs[t] += rs[t+o]; rs2[t] += rs2[t+o]; }
        __syncthreads();
    }
    float mu = rs[0] / D;
    float var = rs2[0] / D - mu*mu;
    float rstd = rsqrtf(var + LN_EPS);
    int bb = tk >> 2, pp = tk & 3;
    float* o = g_ys + (size_t)(bb*NP + n*4 + pp)*D;
    #pragma unroll
    for (int k = 0; k < 4; k++) {
        int d = t + k*256;
        o[d] = (v[k] - mu) * rstd * ln_g[n*D + d] + ln_b[n*D + d];
    }
}

// ---------------- combine: y[b,m,p,d] = sum_n ys * cmb ----------------------
__global__ void k_combine(const float* __restrict__ cmb, float* __restrict__ out) {
    __shared__ float ys_sm[64*128];
    __shared__ float cmb_sm[8*64];
    int t = threadIdx.x;
    int b = blockIdx.z, d0 = blockIdx.y * 128, s0 = blockIdx.x * 128;
    #pragma unroll
    for (int k = 0; k < 32; k++) {
        int i = t + k*256; int np = i >> 7, dd = i & 127;
        ys_sm[np*128 + dd] = g_ys[(size_t)(b*NP + np)*D + d0 + dd];
    }
    int phalf = t >> 7;
    int dd = t & 127;
    for (int tg = 0; tg < 128; tg += 8) {
        __syncthreads();
        #pragma unroll
        for (int k = 0; k < 2; k++) {
            int i = t + k*256; int tk = i >> 6, np = i & 63;
            cmb_sm[tk*64 + np] = cmb[(size_t)(b*S + s0 + tg + tk)*NP + np];
        }
        __syncthreads();
        #pragma unroll 2
        for (int tk = 0; tk < 8; tk++) {
            int s = s0 + tg + tk;
            #pragma unroll
            for (int pi = 0; pi < 2; pi++) {
                int p = phalf*2 + pi;
                float acc = 0.f;
                #pragma unroll
                for (int n = 0; n < NEXP; n++)
                    acc += ys_sm[(n*4+p)*128 + dd] * cmb_sm[tk*64 + n*4 + p];
                out[((size_t)p*B + b)*S*D + (size_t)s*D + d0 + dd] = acc;
            }
        }
    }
}

// ---------------- mutual info loss ------------------------------------------
__global__ void k_mi() {
    __shared__ double red[256];
    int t = threadIdx.x;
    int tok = blockIdx.x * 256 + t;
    int b = tok >> 12;
    double iZb = g_iZb[b];
    double pv[P]; double pm = 0.0;
    #pragma unroll
    for (int p = 0; p < P; p++) { pv[p] = (double)g_epart[tok*P + p] * iZb; pm += pv[p]; }
    double term = 0.0;
    #pragma unroll
    for (int p = 0; p < P; p++) {
        double pt_p = g_ptn[b*P + p] * iZb;
        double ratio = pv[p] / (pm * pt_p) + 1e-10;
        term += pv[p] * log(ratio);
    }
    red[t] = term; __syncthreads();
    for (int o = 128; o > 0; o >>= 1) { if (t < o) red[t] += red[t+o]; __syncthreads(); }
    if (t == 0) atomicAdd(&g_mi, red[0]);
}

__global__ void k_fin(float* __restrict__ out_mi) {
    out_mi[0] = (float)(-g_mi);
}

// ---------------- launch -----------------------------------------------------
extern "C" void kernel_launch(void* const* d_in, const int* in_sizes, int n_in,
                              void* d_out, int out_size) {
    const float* x        = (const float*)d_in[0];
    const float* phi      = (const float*)d_in[1];
    const float* scale    = (const float*)d_in[2];
    const float* task_emb = (const float*)d_in[3];
    const float* W1       = (const float*)d_in[4];
    const float* b1       = (const float*)d_in[5];
    const float* W2       = (const float*)d_in[6];
    const float* b2       = (const float*)d_in[7];
    const float* ln_g     = (const float*)d_in[8];
    const float* ln_b     = (const float*)d_in[9];
    float* out = (float*)d_out;
    float* out_cmb = out + (size_t)P*B*S*D;
    float* out_mi  = out_cmb + (size_t)B*S*NP;

    k_init<<<2048, 256>>>(task_emb);
    k_ph<<<NP, 256>>>(phi, scale);
    k_logits<<<TOK/32, 256>>>(x, out_cmb);
    k_zb<<<1, 256>>>();
    k_xs<<<dim3(8, 8, B), 256>>>(x);
    k_ffn1<<<dim3(NEXP, H/64), 256>>>(W1, b1);
    k_ffn2<<<dim3(NEXP, D/64), 256>>>(W2, b2);
    k_ln<<<NEXP*ETOK, 256>>>(ln_g, ln_b);
    k_combine<<<dim3(32, 8, B), 256>>>(out_cmb, out);
    k_mi<<<TOK/256, 256>>>();
    k_fin<<<1, 1>>>(out_mi);
}